// round 11
// baseline (speedup 1.0000x reference)
#include <cuda_runtime.h>
#include <cstdint>

#define POOL_M 60
#define NC     256
#define HW     3136
#define CHW    (NC * HW)        // 802816
#define NB     64
#define KP     64               // padded K
#define TP     128              // positions per block tile
#define PW     68               // sW pitch (floats): (68*g+tg)%32 = (4g+tg)%32 distinct
#define PP     136              // sP pitch: 136%32==8 -> (8*tg+g)%32 distinct
#define EPSN   1e-8f

__device__ float g_mavg[POOL_M * NC];
__device__ float g_whi[NB * KP];   // tf32-hi bits (as float), K-padded with 0
__device__ float g_wlo[NB * KP];   // f32 residual,            K-padded with 0

// ---------------------------------------------------------------------------
// Kernel 1: mean over H*W, one WARP per (m,c) row.
// ---------------------------------------------------------------------------
__global__ void mean_kernel(const float* __restrict__ pool) {
    const int gw   = (blockIdx.x * blockDim.x + threadIdx.x) >> 5;
    const int lane = threadIdx.x & 31;
    if (gw >= POOL_M * NC) return;
    const float4* p = reinterpret_cast<const float4*>(pool + (size_t)gw * HW);
    float s0 = 0.f, s1 = 0.f;
    #pragma unroll 4
    for (int i = lane; i < HW / 4 - 32; i += 64) {
        float4 a = p[i];
        float4 b = p[i + 32];
        s0 += (a.x + a.y) + (a.z + a.w);
        s1 += (b.x + b.y) + (b.z + b.w);
    }
    if (lane < 16) {
        float4 a = p[768 + lane];
        s0 += (a.x + a.y) + (a.z + a.w);
    }
    float s = s0 + s1;
    #pragma unroll
    for (int o = 16; o > 0; o >>= 1) s += __shfl_down_sync(0xffffffffu, s, o);
    if (lane == 0) g_mavg[gw] = s * (1.0f / (float)HW);
}

// ---------------------------------------------------------------------------
// Kernel 2: cosine + softmax -> pre-split weights g_whi/g_wlo.
// ---------------------------------------------------------------------------
__global__ void cosw_kernel(const float* __restrict__ query) {
    const int b    = blockIdx.x;
    const int t    = threadIdx.x;
    const int wid  = t >> 5;
    const int lane = t & 31;

    __shared__ float sq[NC];
    __shared__ float scos[NB];
    __shared__ float s_wfin[NB];
    __shared__ float red[8];
    __shared__ float s_qn;

    const float qv = query[b * NC + t];
    sq[t] = qv;

    float s = qv * qv;
    #pragma unroll
    for (int o = 16; o > 0; o >>= 1) s += __shfl_down_sync(0xffffffffu, s, o);
    if (lane == 0) red[wid] = s;
    __syncthreads();
    if (t == 0) {
        float tt = 0.f;
        #pragma unroll
        for (int i = 0; i < 8; i++) tt += red[i];
        s_qn = fmaxf(sqrtf(tt), EPSN);
    }
    __syncthreads();

    for (int m = wid; m < POOL_M; m += 8) {
        float d = 0.f, n2 = 0.f;
        #pragma unroll
        for (int c = lane; c < NC; c += 32) {
            const float mv = g_mavg[m * NC + c];
            d  = fmaf(mv, sq[c], d);
            n2 = fmaf(mv, mv, n2);
        }
        #pragma unroll
        for (int o = 16; o > 0; o >>= 1) {
            d  += __shfl_down_sync(0xffffffffu, d,  o);
            n2 += __shfl_down_sync(0xffffffffu, n2, o);
        }
        if (lane == 0) scos[m] = d / (s_qn * fmaxf(sqrtf(n2), EPSN));
    }
    __syncthreads();

    if (wid == 0) {
        const bool hi = (lane + 32) < POOL_M;
        float a  = scos[lane];
        float c2 = hi ? scos[lane + 32] : -1e30f;
        float mx = fmaxf(a, c2);
        #pragma unroll
        for (int o = 16; o > 0; o >>= 1) mx = fmaxf(mx, __shfl_xor_sync(0xffffffffu, mx, o));
        float e1 = __expf(a - mx);
        float e2 = hi ? __expf(c2 - mx) : 0.f;
        float sm = e1 + e2;
        #pragma unroll
        for (int o = 16; o > 0; o >>= 1) sm += __shfl_xor_sync(0xffffffffu, sm, o);
        const float inv = 1.0f / sm;
        s_wfin[lane] = e1 * inv;
        if (lane + 32 < NB) s_wfin[lane + 32] = hi ? (e2 * inv) : 0.f;
    }
    __syncthreads();

    if (t < KP) {
        const float w = (t < POOL_M) ? s_wfin[t] : 0.f;
        uint32_t hb;
        asm("cvt.rna.tf32.f32 %0, %1;" : "=r"(hb) : "f"(w));
        const float hf = __uint_as_float(hb);
        g_whi[b * KP + t] = hf;
        g_wlo[b * KP + t] = w - hf;
    }
}

// ---------------------------------------------------------------------------
// Kernel 3: out = W @ P, m16n8k8 TF32 MMA, 3xTF32, all conversions hoisted.
// Tile 64 b x 128 pos, K=64. 8 warps = 4 brow(16b) x 2 pcol(64pos); nt=8.
// Dynamic smem: sWhi|sWlo [64xPW], sPhi|sPlo [64xPP] = 104448 B.
// ---------------------------------------------------------------------------
__device__ __forceinline__ void mma_tf32(float* d, const uint32_t* a,
                                         uint32_t b0, uint32_t b1) {
    asm volatile(
        "mma.sync.aligned.m16n8k8.row.col.f32.tf32.tf32.f32 "
        "{%0,%1,%2,%3}, {%4,%5,%6,%7}, {%8,%9}, {%0,%1,%2,%3};"
        : "+f"(d[0]), "+f"(d[1]), "+f"(d[2]), "+f"(d[3])
        : "r"(a[0]), "r"(a[1]), "r"(a[2]), "r"(a[3]), "r"(b0), "r"(b1));
}

#define SW_ELEMS (NB * PW)
#define SP_ELEMS (KP * PP)

__global__ void __launch_bounds__(256)
wsum_kernel(const float* __restrict__ pool, float* __restrict__ out) {
    extern __shared__ __align__(16) float smem[];
    float* sWhi = smem;                       // [64][PW]
    float* sWlo = sWhi + SW_ELEMS;
    float* sPhi = sWlo + SW_ELEMS;            // [64][PP]
    float* sPlo = sPhi + SP_ELEMS;

    const int tid  = threadIdx.x;
    const int warp = tid >> 5;
    const int lane = tid & 31;
    const int g    = lane >> 2;      // 0..7
    const int tg   = lane & 3;       // 0..3
    const int brow = warp & 3;       // 4 groups of 16 b
    const int pcol = warp >> 2;      // 0..1, 64 pos each
    const long long posbase = (long long)blockIdx.x * TP;

    // stage pre-split weights (pad cols of pitch never read)
    for (int i = tid; i < NB * KP; i += 256) {
        const int b = i >> 6, k = i & 63;
        sWhi[b * PW + k] = g_whi[i];
        sWlo[b * PW + k] = g_wlo[i];
    }
    // stage pool tile, converting hi/lo once
    for (int i = tid; i < KP * (TP / 4); i += 256) {   // 2048 float4 slots
        const int m = i >> 5;        // 0..63
        const int v = i & 31;        // float4 within row
        float4 val = make_float4(0.f, 0.f, 0.f, 0.f);
        if (m < POOL_M)
            val = *reinterpret_cast<const float4*>(pool + (long long)m * CHW + posbase + v * 4);
        float4 h, l;
        uint32_t u;
        asm("cvt.rna.tf32.f32 %0, %1;" : "=r"(u) : "f"(val.x)); h.x = __uint_as_float(u); l.x = val.x - h.x;
        asm("cvt.rna.tf32.f32 %0, %1;" : "=r"(u) : "f"(val.y)); h.y = __uint_as_float(u); l.y = val.y - h.y;
        asm("cvt.rna.tf32.f32 %0, %1;" : "=r"(u) : "f"(val.z)); h.z = __uint_as_float(u); l.z = val.z - h.z;
        asm("cvt.rna.tf32.f32 %0, %1;" : "=r"(u) : "f"(val.w)); h.w = __uint_as_float(u); l.w = val.w - h.w;
        *reinterpret_cast<float4*>(&sPhi[m * PP + v * 4]) = h;
        *reinterpret_cast<float4*>(&sPlo[m * PP + v * 4]) = l;
    }
    __syncthreads();

    float acc[8][4];
    #pragma unroll
    for (int nt = 0; nt < 8; nt++)
        #pragma unroll
        for (int j = 0; j < 4; j++) acc[nt][j] = 0.f;

    const uint32_t* pWhi = reinterpret_cast<const uint32_t*>(sWhi + (brow * 16 + g) * PW + tg);
    const uint32_t* pWlo = reinterpret_cast<const uint32_t*>(sWlo + (brow * 16 + g) * PW + tg);
    const int colbase = pcol * 64 + g;

    #pragma unroll
    for (int kb = 0; kb < 8; kb++) {
        uint32_t ahi[4], alo[4];
        ahi[0] = pWhi[kb * 8];               alo[0] = pWlo[kb * 8];
        ahi[1] = pWhi[kb * 8 + 8 * PW];      alo[1] = pWlo[kb * 8 + 8 * PW];
        ahi[2] = pWhi[kb * 8 + 4];           alo[2] = pWlo[kb * 8 + 4];
        ahi[3] = pWhi[kb * 8 + 4 + 8 * PW];  alo[3] = pWlo[kb * 8 + 4 + 8 * PW];

        const int r0 = (kb * 8 + tg) * PP + colbase;
        const int r1 = (kb * 8 + tg + 4) * PP + colbase;
        #pragma unroll
        for (int nt = 0; nt < 8; nt++) {
            const uint32_t bhi0 = __float_as_uint(sPhi[r0 + nt * 8]);
            const uint32_t bhi1 = __float_as_uint(sPhi[r1 + nt * 8]);
            const uint32_t blo0 = __float_as_uint(sPlo[r0 + nt * 8]);
            const uint32_t blo1 = __float_as_uint(sPlo[r1 + nt * 8]);
            mma_tf32(acc[nt], ahi, bhi0, bhi1);
            mma_tf32(acc[nt], ahi, blo0, blo1);
            mma_tf32(acc[nt], alo, bhi0, bhi1);
        }
    }

    // epilogue
    const int bq = brow * 16 + g;
    const long long pb = posbase + pcol * 64 + tg * 2;
    float* o0 = out + (long long)bq * CHW + pb;
    float* o1 = out + (long long)(bq + 8) * CHW + pb;
    #pragma unroll
    for (int nt = 0; nt < 8; nt++) {
        float2 lo; lo.x = acc[nt][0]; lo.y = acc[nt][1];
        float2 hi; hi.x = acc[nt][2]; hi.y = acc[nt][3];
        *reinterpret_cast<float2*>(o0 + nt * 8) = lo;
        *reinterpret_cast<float2*>(o1 + nt * 8) = hi;
    }
}

// ---------------------------------------------------------------------------
extern "C" void kernel_launch(void* const* d_in, const int* in_sizes, int n_in,
                              void* d_out, int out_size) {
    const float* pool  = (const float*)d_in[0];   // [60,256,56,56]
    const float* query = (const float*)d_in[1];   // [64,256]
    float* out = (float*)d_out;                   // [64,256,56,56]

    const int smem_bytes = (2 * SW_ELEMS + 2 * SP_ELEMS) * (int)sizeof(float);  // 104448
    cudaFuncSetAttribute(wsum_kernel, cudaFuncAttributeMaxDynamicSharedMemorySize, smem_bytes);

    mean_kernel<<<(POOL_M * NC) / 8, 256>>>(pool);
    cosw_kernel<<<NB, 256>>>(query);
    wsum_kernel<<<CHW / TP, 256, smem_bytes>>>(pool, out);
}

// round 12
// speedup vs baseline: 1.6020x; 1.6020x over previous
#include <cuda_runtime.h>
#include <cstdint>

#define POOL_M 60
#define NC     256
#define HW     3136
#define CHW    (NC * HW)        // 802816
#define NB     64
#define KP     64               // padded K
#define PW     68               // sW pitch (floats)
#define PP     72               // sP pitch (floats)
#define NTILE  (CHW / 64)       // 12544 position tiles of 64
#define GRID_W 592              // 4 blocks/SM * 148
#define EPSN   1e-8f

__device__ float g_mavg[POOL_M * NC];
__device__ float g_w[NB * POOL_M];

// ---------------------------------------------------------------------------
// Kernel 1: mean over H*W, one WARP per (m,c) row.
// ---------------------------------------------------------------------------
__global__ void mean_kernel(const float* __restrict__ pool) {
    const int gw   = (blockIdx.x * blockDim.x + threadIdx.x) >> 5;
    const int lane = threadIdx.x & 31;
    if (gw >= POOL_M * NC) return;
    const float4* p = reinterpret_cast<const float4*>(pool + (size_t)gw * HW);
    float s0 = 0.f, s1 = 0.f;
    #pragma unroll 4
    for (int i = lane; i < HW / 4 - 32; i += 64) {
        float4 a = p[i];
        float4 b = p[i + 32];
        s0 += (a.x + a.y) + (a.z + a.w);
        s1 += (b.x + b.y) + (b.z + b.w);
    }
    if (lane < 16) {
        float4 a = p[768 + lane];
        s0 += (a.x + a.y) + (a.z + a.w);
    }
    float s = s0 + s1;
    #pragma unroll
    for (int o = 16; o > 0; o >>= 1) s += __shfl_down_sync(0xffffffffu, s, o);
    if (lane == 0) g_mavg[gw] = s * (1.0f / (float)HW);
}

// ---------------------------------------------------------------------------
// Kernel 2: cosine + softmax -> g_w[b][m].
// ---------------------------------------------------------------------------
__global__ void cosw_kernel(const float* __restrict__ query) {
    const int b    = blockIdx.x;
    const int t    = threadIdx.x;
    const int wid  = t >> 5;
    const int lane = t & 31;

    __shared__ float sq[NC];
    __shared__ float scos[NB];
    __shared__ float red[8];
    __shared__ float s_qn;

    const float qv = query[b * NC + t];
    sq[t] = qv;

    float s = qv * qv;
    #pragma unroll
    for (int o = 16; o > 0; o >>= 1) s += __shfl_down_sync(0xffffffffu, s, o);
    if (lane == 0) red[wid] = s;
    __syncthreads();
    if (t == 0) {
        float tt = 0.f;
        #pragma unroll
        for (int i = 0; i < 8; i++) tt += red[i];
        s_qn = fmaxf(sqrtf(tt), EPSN);
    }
    __syncthreads();

    for (int m = wid; m < POOL_M; m += 8) {
        float d = 0.f, n2 = 0.f;
        #pragma unroll
        for (int c = lane; c < NC; c += 32) {
            const float mv = g_mavg[m * NC + c];
            d  = fmaf(mv, sq[c], d);
            n2 = fmaf(mv, mv, n2);
        }
        #pragma unroll
        for (int o = 16; o > 0; o >>= 1) {
            d  += __shfl_down_sync(0xffffffffu, d,  o);
            n2 += __shfl_down_sync(0xffffffffu, n2, o);
        }
        if (lane == 0) scos[m] = d / (s_qn * fmaxf(sqrtf(n2), EPSN));
    }
    __syncthreads();

    if (wid == 0) {
        const bool hi = (lane + 32) < POOL_M;
        float a  = scos[lane];
        float c2 = hi ? scos[lane + 32] : -1e30f;
        float mx = fmaxf(a, c2);
        #pragma unroll
        for (int o = 16; o > 0; o >>= 1) mx = fmaxf(mx, __shfl_xor_sync(0xffffffffu, mx, o));
        float e1 = __expf(a - mx);
        float e2 = hi ? __expf(c2 - mx) : 0.f;
        float sm = e1 + e2;
        #pragma unroll
        for (int o = 16; o > 0; o >>= 1) sm += __shfl_xor_sync(0xffffffffu, sm, o);
        const float inv = 1.0f / sm;
        g_w[b * POOL_M + lane] = e1 * inv;
        if (hi) g_w[b * POOL_M + lane + 32] = e2 * inv;
    }
}

// ---------------------------------------------------------------------------
// Kernel 3: persistent, cp.async double-buffered version of the R6 TF32 MMA.
// Each block owns ~21 tiles of 64 positions; prefetch tile t+1 while
// computing tile t. Compute body identical to the proven R6 kernel.
// ---------------------------------------------------------------------------
__device__ __forceinline__ void mma_tf32(float* d, const uint32_t* a,
                                         uint32_t b0, uint32_t b1) {
    asm volatile(
        "mma.sync.aligned.m16n8k8.row.col.f32.tf32.tf32.f32 "
        "{%0,%1,%2,%3}, {%4,%5,%6,%7}, {%8,%9}, {%0,%1,%2,%3};"
        : "+f"(d[0]), "+f"(d[1]), "+f"(d[2]), "+f"(d[3])
        : "r"(a[0]), "r"(a[1]), "r"(a[2]), "r"(a[3]), "r"(b0), "r"(b1));
}

__device__ __forceinline__ uint32_t f32_to_tf32(float x) {
    uint32_t r;
    asm("cvt.rna.tf32.f32 %0, %1;" : "=r"(r) : "f"(x));
    return r;
}

__device__ __forceinline__ void cp_async16(float* smem_dst, const float* gmem_src) {
    uint32_t s = (uint32_t)__cvta_generic_to_shared(smem_dst);
    asm volatile("cp.async.cg.shared.global [%0], [%1], 16;" :: "r"(s), "l"(gmem_src) : "memory");
}

__device__ __forceinline__ void stage_tile(const float* __restrict__ pool,
                                           float* __restrict__ sP, int t, int tid) {
    const long long posbase = (long long)t * 64;
    #pragma unroll
    for (int i = tid; i < POOL_M * 16; i += 256) {   // 960 x 16B
        const int m = i >> 4, v = i & 15;
        cp_async16(&sP[m * PP + v * 4], pool + (long long)m * CHW + posbase + v * 4);
    }
}

#define SW_ELEMS (NB * PW)          // 4352
#define SP_ELEMS (KP * PP)          // 4608

__global__ void __launch_bounds__(256)
wsum_kernel(const float* __restrict__ pool, float* __restrict__ out) {
    extern __shared__ __align__(16) float smem[];
    float* sW  = smem;                               // [64][68]
    float* sP0 = smem + SW_ELEMS;                    // [64][72]
    float* sP1 = sP0 + SP_ELEMS;

    const int tid  = threadIdx.x;
    const int warp = tid >> 5;
    const int lane = tid & 31;
    const int g    = lane >> 2;      // 0..7
    const int tg   = lane & 3;       // 0..3
    const int brow = warp & 3;       // 4 groups of 16 b
    const int pcol = warp >> 2;      // 0..1, 32 pos each

    // stage weights once (zero-padded K)
    for (int i = tid; i < NB * KP; i += 256) {
        const int b = i >> 6, k = i & 63;
        sW[b * PW + k] = (k < POOL_M) ? g_w[b * POOL_M + k] : 0.f;
    }
    // zero pad rows 60..63 of both pool buffers (never touched by cp.async)
    for (int i = tid; i < 2 * 4 * PP; i += 256) {
        const int buf = i / (4 * PP);
        const int j   = i % (4 * PP);
        (buf ? sP1 : sP0)[POOL_M * PP + j] = 0.f;
    }

    const uint32_t* pW = reinterpret_cast<const uint32_t*>(sW + (brow * 16 + g) * PW + tg);

    int t = blockIdx.x;
    stage_tile(pool, sP0, t, tid);
    asm volatile("cp.async.commit_group;" ::: "memory");
    asm volatile("cp.async.wait_group 0;" ::: "memory");
    __syncthreads();

    int cur = 0;
    for (; t < NTILE; t += GRID_W) {
        float* sPc = cur ? sP1 : sP0;
        float* sPn = cur ? sP0 : sP1;
        const int tn = t + GRID_W;
        if (tn < NTILE) {
            stage_tile(pool, sPn, tn, tid);
            asm volatile("cp.async.commit_group;" ::: "memory");
        }

        // ---- compute tile t (identical to R6) ----
        float acc[4][4];
        #pragma unroll
        for (int nt = 0; nt < 4; nt++)
            #pragma unroll
            for (int j = 0; j < 4; j++) acc[nt][j] = 0.f;

        const float* pP = &sPc[tg * PP + pcol * 32 + g];

        #pragma unroll
        for (int kb = 0; kb < 8; kb++) {
            float a0 = __uint_as_float(pW[kb * 8]);
            float a1 = __uint_as_float(pW[kb * 8 + 8 * PW]);
            float a2 = __uint_as_float(pW[kb * 8 + 4]);
            float a3 = __uint_as_float(pW[kb * 8 + 4 + 8 * PW]);
            uint32_t ahi[4], alo[4];
            ahi[0] = f32_to_tf32(a0); alo[0] = __float_as_uint(a0 - __uint_as_float(ahi[0]));
            ahi[1] = f32_to_tf32(a1); alo[1] = __float_as_uint(a1 - __uint_as_float(ahi[1]));
            ahi[2] = f32_to_tf32(a2); alo[2] = __float_as_uint(a2 - __uint_as_float(ahi[2]));
            ahi[3] = f32_to_tf32(a3); alo[3] = __float_as_uint(a3 - __uint_as_float(ahi[3]));

            #pragma unroll
            for (int nt = 0; nt < 4; nt++) {
                const float b0f = pP[(kb * 8)     * PP + nt * 8];
                const float b1f = pP[(kb * 8 + 4) * PP + nt * 8];
                const uint32_t bhi0 = f32_to_tf32(b0f);
                const uint32_t bhi1 = f32_to_tf32(b1f);
                const uint32_t blo0 = __float_as_uint(b0f - __uint_as_float(bhi0));
                const uint32_t blo1 = __float_as_uint(b1f - __uint_as_float(bhi1));
                mma_tf32(acc[nt], ahi, bhi0, bhi1);
                mma_tf32(acc[nt], ahi, blo0, blo1);
                mma_tf32(acc[nt], alo, bhi0, bhi1);
            }
        }

        // epilogue
        const long long posbase = (long long)t * 64;
        const int bq = brow * 16 + g;
        const long long pb = posbase + pcol * 32 + tg * 2;
        float* o0 = out + (long long)bq * CHW + pb;
        float* o1 = out + (long long)(bq + 8) * CHW + pb;
        #pragma unroll
        for (int nt = 0; nt < 4; nt++) {
            float2 lo; lo.x = acc[nt][0]; lo.y = acc[nt][1];
            float2 hi; hi.x = acc[nt][2]; hi.y = acc[nt][3];
            *reinterpret_cast<float2*>(o0 + nt * 8) = lo;
            *reinterpret_cast<float2*>(o1 + nt * 8) = hi;
        }

        if (tn < NTILE)
            asm volatile("cp.async.wait_group 0;" ::: "memory");
        __syncthreads();
        cur ^= 1;
    }
}

// ---------------------------------------------------------------------------
extern "C" void kernel_launch(void* const* d_in, const int* in_sizes, int n_in,
                              void* d_out, int out_size) {
    const float* pool  = (const float*)d_in[0];   // [60,256,56,56]
    const float* query = (const float*)d_in[1];   // [64,256]
    float* out = (float*)d_out;                   // [64,256,56,56]

    const int smem_bytes = (SW_ELEMS + 2 * SP_ELEMS) * (int)sizeof(float);  // 54272
    cudaFuncSetAttribute(wsum_kernel, cudaFuncAttributeMaxDynamicSharedMemorySize, smem_bytes);

    mean_kernel<<<(POOL_M * NC) / 8, 256>>>(pool);
    cosw_kernel<<<NB, 256>>>(query);
    wsum_kernel<<<GRID_W, 256, smem_bytes>>>(pool, out);
}

// round 15
// speedup vs baseline: 1.7176x; 1.0721x over previous
#include <cuda_runtime.h>
#include <cuda_bf16.h>
#include <cstdint>

#define POOL_M 60
#define NC     256
#define HW     3136
#define CHW    (NC * HW)        // 802816
#define NB     64
#define NKP    32               // k-pairs (K padded to 64)
#define SWP    36               // sW pitch (u32)
#define SPP    68               // sP pitch (u32)
#define NTILE  (CHW / 64)       // 12544
#define GRID_W 592
#define EPSN   1e-8f

__device__ float    g_mavg[POOL_M * NC];
__device__ uint32_t g_whi[NB * NKP];   // bf16x2 k-pairs, hi part
__device__ uint32_t g_wlo[NB * NKP];   // bf16x2 k-pairs, residual

// ---------------------------------------------------------------------------
// Kernel 1: mean over H*W, one WARP per (m,c) row.
// ---------------------------------------------------------------------------
__global__ void mean_kernel(const float* __restrict__ pool) {
    const int gw   = (blockIdx.x * blockDim.x + threadIdx.x) >> 5;
    const int lane = threadIdx.x & 31;
    if (gw >= POOL_M * NC) return;
    const float4* p = reinterpret_cast<const float4*>(pool + (size_t)gw * HW);
    float s0 = 0.f, s1 = 0.f;
    #pragma unroll 4
    for (int i = lane; i < HW / 4 - 32; i += 64) {
        float4 a = p[i];
        float4 b = p[i + 32];
        s0 += (a.x + a.y) + (a.z + a.w);
        s1 += (b.x + b.y) + (b.z + b.w);
    }
    if (lane < 16) {
        float4 a = p[768 + lane];
        s0 += (a.x + a.y) + (a.z + a.w);
    }
    float s = s0 + s1;
    #pragma unroll
    for (int o = 16; o > 0; o >>= 1) s += __shfl_down_sync(0xffffffffu, s, o);
    if (lane == 0) g_mavg[gw] = s * (1.0f / (float)HW);
}

// ---------------------------------------------------------------------------
// bf16 split helpers: value = hi + lo (+ ~2^-17 rel dropped)
// pair packing: .x (low half) = even-k element, .y (high) = odd-k element
// ---------------------------------------------------------------------------
__device__ __forceinline__ void split2(float e, float o, uint32_t& hi, uint32_t& lo) {
    __nv_bfloat16 he = __float2bfloat16_rn(e);
    __nv_bfloat16 ho = __float2bfloat16_rn(o);
    const float re = e - __bfloat162float(he);
    const float ro = o - __bfloat162float(ho);
    __nv_bfloat162 H; H.x = he; H.y = ho;
    __nv_bfloat162 L; L.x = __float2bfloat16_rn(re); L.y = __float2bfloat16_rn(ro);
    hi = *reinterpret_cast<uint32_t*>(&H);
    lo = *reinterpret_cast<uint32_t*>(&L);
}

// ---------------------------------------------------------------------------
// Kernel 2: cosine + softmax -> pre-split packed weights g_whi/g_wlo.
// ---------------------------------------------------------------------------
__global__ void cosw_kernel(const float* __restrict__ query) {
    const int b    = blockIdx.x;
    const int t    = threadIdx.x;
    const int wid  = t >> 5;
    const int lane = t & 31;

    __shared__ float sq[NC];
    __shared__ float scos[NB];
    __shared__ float s_wfin[NB];
    __shared__ float red[8];
    __shared__ float s_qn;

    const float qv = query[b * NC + t];
    sq[t] = qv;

    float s = qv * qv;
    #pragma unroll
    for (int o = 16; o > 0; o >>= 1) s += __shfl_down_sync(0xffffffffu, s, o);
    if (lane == 0) red[wid] = s;
    __syncthreads();
    if (t == 0) {
        float tt = 0.f;
        #pragma unroll
        for (int i = 0; i < 8; i++) tt += red[i];
        s_qn = fmaxf(sqrtf(tt), EPSN);
    }
    __syncthreads();

    for (int m = wid; m < POOL_M; m += 8) {
        float d = 0.f, n2 = 0.f;
        #pragma unroll
        for (int c = lane; c < NC; c += 32) {
            const float mv = g_mavg[m * NC + c];
            d  = fmaf(mv, sq[c], d);
            n2 = fmaf(mv, mv, n2);
        }
        #pragma unroll
        for (int o = 16; o > 0; o >>= 1) {
            d  += __shfl_down_sync(0xffffffffu, d,  o);
            n2 += __shfl_down_sync(0xffffffffu, n2, o);
        }
        if (lane == 0) scos[m] = d / (s_qn * fmaxf(sqrtf(n2), EPSN));
    }
    __syncthreads();

    if (wid == 0) {
        const bool hi = (lane + 32) < POOL_M;
        float a  = scos[lane];
        float c2 = hi ? scos[lane + 32] : -1e30f;
        float mx = fmaxf(a, c2);
        #pragma unroll
        for (int o = 16; o > 0; o >>= 1) mx = fmaxf(mx, __shfl_xor_sync(0xffffffffu, mx, o));
        float e1 = __expf(a - mx);
        float e2 = hi ? __expf(c2 - mx) : 0.f;
        float sm = e1 + e2;
        #pragma unroll
        for (int o = 16; o > 0; o >>= 1) sm += __shfl_xor_sync(0xffffffffu, sm, o);
        const float inv = 1.0f / sm;
        s_wfin[lane] = e1 * inv;
        if (lane + 32 < NB) s_wfin[lane + 32] = hi ? (e2 * inv) : 0.f;
    }
    __syncthreads();

    if (t < NKP) {
        const float w0 = (2 * t     < POOL_M) ? s_wfin[2 * t]     : 0.f;
        const float w1 = (2 * t + 1 < POOL_M) ? s_wfin[2 * t + 1] : 0.f;
        uint32_t hi, lo;
        split2(w0, w1, hi, lo);
        g_whi[b * NKP + t] = hi;
        g_wlo[b * NKP + t] = lo;
    }
}

// ---------------------------------------------------------------------------
// Kernel 3: persistent 3xBF16 m16n8k16 MMA, fragments pre-packed in smem.
// Tile 64 b x 64 pos; 8 warps = 4 brow x 2 pcol; nt = 4 per warp.
// ---------------------------------------------------------------------------
__device__ __forceinline__ void mma_bf16(float* d, const uint32_t* a,
                                         uint32_t b0, uint32_t b1) {
    asm volatile(
        "mma.sync.aligned.m16n8k16.row.col.f32.bf16.bf16.f32 "
        "{%0,%1,%2,%3}, {%4,%5,%6,%7}, {%8,%9}, {%0,%1,%2,%3};"
        : "+f"(d[0]), "+f"(d[1]), "+f"(d[2]), "+f"(d[3])
        : "r"(a[0]), "r"(a[1]), "r"(a[2]), "r"(a[3]), "r"(b0), "r"(b1));
}

#define SW_U32 (NB * SWP)          // 2304
#define SP_U32 (NKP * SPP)         // 2176

__global__ void __launch_bounds__(256)
wsum_kernel(const float* __restrict__ pool, float* __restrict__ out) {
    extern __shared__ __align__(16) uint32_t smem[];
    uint32_t* sWhi = smem;                     // [64][SWP]
    uint32_t* sWlo = sWhi + SW_U32;
    uint32_t* sPhi[2] = { sWlo + SW_U32, sWlo + SW_U32 + 2 * SP_U32 };
    uint32_t* sPlo[2] = { sPhi[0] + SP_U32,  sPhi[1] + SP_U32 };

    const int tid  = threadIdx.x;
    const int warp = tid >> 5;
    const int lane = tid & 31;
    const int g    = lane >> 2;
    const int tg   = lane & 3;
    const int brow = warp & 3;
    const int pcol = warp >> 2;

    // stage packed weights once
    for (int i = tid; i < NB * NKP; i += 256) {
        const int b = i >> 5, kp = i & 31;
        sWhi[b * SWP + kp] = g_whi[i];
        sWlo[b * SWP + kp] = g_wlo[i];
    }
    // zero pad k-pair rows 30,31 of all 4 P buffers (never written by staging)
    for (int i = tid; i < 4 * 2 * SPP; i += 256) {
        const int buf = i / (2 * SPP);
        const int w   = i % (2 * SPP);
        uint32_t* base = (buf & 2) ? (buf & 1 ? sPlo[1] : sPhi[1])
                                   : (buf & 1 ? sPlo[0] : sPhi[0]);
        base[30 * SPP + w] = 0u;
    }

    // staging assignment: unit = (kpair, quad); thread covers kp1 and kp1+16
    const int kp1 = tid >> 4;          // 0..15
    const int kp2 = kp1 + 16;          // 16..31 (valid if < 30)
    const int q   = tid & 15;
    const bool u2 = (kp2 < 30);

    float4 ra, rb, rc, rd;

    // ---- prologue: load + convert tile blockIdx.x into buffer 0 ----
    int t = blockIdx.x;
    {
        const long long base = (long long)t * 64 + 4 * q;
        ra = *reinterpret_cast<const float4*>(pool + (long long)(2 * kp1)     * CHW + base);
        rb = *reinterpret_cast<const float4*>(pool + (long long)(2 * kp1 + 1) * CHW + base);
        if (u2) {
            rc = *reinterpret_cast<const float4*>(pool + (long long)(2 * kp2)     * CHW + base);
            rd = *reinterpret_cast<const float4*>(pool + (long long)(2 * kp2 + 1) * CHW + base);
        }
        uint4 H, L;
        split2(ra.x, rb.x, H.x, L.x); split2(ra.y, rb.y, H.y, L.y);
        split2(ra.z, rb.z, H.z, L.z); split2(ra.w, rb.w, H.w, L.w);
        *reinterpret_cast<uint4*>(&sPhi[0][kp1 * SPP + 4 * q]) = H;
        *reinterpret_cast<uint4*>(&sPlo[0][kp1 * SPP + 4 * q]) = L;
        if (u2) {
            split2(rc.x, rd.x, H.x, L.x); split2(rc.y, rd.y, H.y, L.y);
            split2(rc.z, rd.z, H.z, L.z); split2(rc.w, rd.w, H.w, L.w);
            *reinterpret_cast<uint4*>(&sPhi[0][kp2 * SPP + 4 * q]) = H;
            *reinterpret_cast<uint4*>(&sPlo[0][kp2 * SPP + 4 * q]) = L;
        }
    }
    __syncthreads();

    const uint32_t* pWhi = sWhi + (brow * 16 + g) * SWP + tg;
    const uint32_t* pWlo = sWlo + (brow * 16 + g) * SWP + tg;
    const int colb = pcol * 32 + g;

    int cur = 0;
    for (; t < NTILE; t += GRID_W) {
        const int tn = t + GRID_W;
        // prefetch next tile into registers
        if (tn < NTILE) {
            const long long base = (long long)tn * 64 + 4 * q;
            ra = *reinterpret_cast<const float4*>(pool + (long long)(2 * kp1)     * CHW + base);
            rb = *reinterpret_cast<const float4*>(pool + (long long)(2 * kp1 + 1) * CHW + base);
            if (u2) {
                rc = *reinterpret_cast<const float4*>(pool + (long long)(2 * kp2)     * CHW + base);
                rd = *reinterpret_cast<const float4*>(pool + (long long)(2 * kp2 + 1) * CHW + base);
            }
        }

        // ---- compute tile t from buffer cur ----
        const uint32_t* Ph = sPhi[cur];
        const uint32_t* Pl = sPlo[cur];

        float acc[4][4];
        #pragma unroll
        for (int nt = 0; nt < 4; nt++)
            #pragma unroll
            for (int j = 0; j < 4; j++) acc[nt][j] = 0.f;

        #pragma unroll
        for (int kb = 0; kb < 4; kb++) {
            uint32_t ahi[4], alo[4];
            ahi[0] = pWhi[kb * 8];              alo[0] = pWlo[kb * 8];
            ahi[1] = pWhi[kb * 8 + 8 * SWP];    alo[1] = pWlo[kb * 8 + 8 * SWP];
            ahi[2] = pWhi[kb * 8 + 4];          alo[2] = pWlo[kb * 8 + 4];
            ahi[3] = pWhi[kb * 8 + 4 + 8*SWP];  alo[3] = pWlo[kb * 8 + 4 + 8*SWP];

            const int r0 = (kb * 8 + tg) * SPP + colb;
            const int r1 = (kb * 8 + tg + 4) * SPP + colb;
            #pragma unroll
            for (int nt = 0; nt < 4; nt++) {
                const uint32_t bh0 = Ph[r0 + nt * 8];
                const uint32_t bh1 = Ph[r1 + nt * 8];
                const uint32_t bl0 = Pl[r0 + nt * 8];
                const uint32_t bl1 = Pl[r1 + nt * 8];
                mma_bf16(acc[nt], ahi, bh0, bh1);
                mma_bf16(acc[nt], ahi, bl0, bl1);
                mma_bf16(acc[nt], alo, bh0, bh1);
            }
        }

        // epilogue
        const long long posbase = (long long)t * 64;
        const int bq = brow * 16 + g;
        const long long pb = posbase + pcol * 32 + tg * 2;
        float* o0 = out + (long long)bq * CHW + pb;
        float* o1 = out + (long long)(bq + 8) * CHW + pb;
        #pragma unroll
        for (int nt = 0; nt < 4; nt++) {
            float2 lo; lo.x = acc[nt][0]; lo.y = acc[nt][1];
            float2 hi; hi.x = acc[nt][2]; hi.y = acc[nt][3];
            *reinterpret_cast<float2*>(o0 + nt * 8) = lo;
            *reinterpret_cast<float2*>(o1 + nt * 8) = hi;
        }

        // convert prefetched regs into the other buffer
        if (tn < NTILE) {
            uint32_t* Nh = sPhi[cur ^ 1];
            uint32_t* Nl = sPlo[cur ^ 1];
            uint4 H, L;
            split2(ra.x, rb.x, H.x, L.x); split2(ra.y, rb.y, H.y, L.y);
            split2(ra.z, rb.z, H.z, L.z); split2(ra.w, rb.w, H.w, L.w);
            *reinterpret_cast<uint4*>(&Nh[kp1 * SPP + 4 * q]) = H;
            *reinterpret_cast<uint4*>(&Nl[kp1 * SPP + 4 * q]) = L;
            if (u2) {
                split2(rc.x, rd.x, H.x, L.x); split2(rc.y, rd.y, H.y, L.y);
                split2(rc.z, rd.z, H.z, L.z); split2(rc.w, rd.w, H.w, L.w);
                *reinterpret_cast<uint4*>(&Nh[kp2 * SPP + 4 * q]) = H;
                *reinterpret_cast<uint4*>(&Nl[kp2 * SPP + 4 * q]) = L;
            }
        }
        __syncthreads();
        cur ^= 1;
    }
}

// ---------------------------------------------------------------------------
extern "C" void kernel_launch(void* const* d_in, const int* in_sizes, int n_in,
                              void* d_out, int out_size) {
    const float* pool  = (const float*)d_in[0];   // [60,256,56,56]
    const float* query = (const float*)d_in[1];   // [64,256]
    float* out = (float*)d_out;                   // [64,256,56,56]

    const int smem_bytes = (2 * SW_U32 + 4 * SP_U32) * (int)sizeof(uint32_t); // 53248
    cudaFuncSetAttribute(wsum_kernel, cudaFuncAttributeMaxDynamicSharedMemorySize, smem_bytes);

    mean_kernel<<<(POOL_M * NC) / 8, 256>>>(pool);
    cosw_kernel<<<NB, 256>>>(query);
    wsum_kernel<<<GRID_W, 256, smem_bytes>>>(pool, out);
}